// round 7
// baseline (speedup 1.0000x reference)
#include <cuda_runtime.h>
#include <cstdint>
#include <cstddef>

typedef unsigned long long ull;
#define DINLINE __device__ __forceinline__

namespace {
constexpr int Tlen = 512, OUTW = 24;
constexpr int CL = 8, Br = 16, NTHR = 128;
constexpr int H1S = 260, H2S = 130, XSS = 68;

constexpr int OFF_R1 = 8;                    // [256][96] gate-interleaved
constexpr int OFF_K1 = OFF_R1 + 24576;       // [64][96]
constexpr int OFF_K2 = OFF_K1 + 6144;        // [256][48]
constexpr int OFF_R2 = OFF_K2 + 12288;       // [128][48]
constexpr int OFF_H1 = OFF_R2 + 6144;        // [16][260]
constexpr int OFF_H2 = OFF_H1 + Br * H1S;    // [16][130]
constexpr int OFF_XS = OFF_H2 + Br * H2S;    // [16][68]
constexpr int SMEM_FLOATS = OFF_XS + Br * XSS;          // 56488
constexpr size_t SMEM_BYTES = SMEM_FLOATS * sizeof(float);  // 225952
}

DINLINE float sigf(float v) { return __fdividef(1.0f, 1.0f + __expf(-v)); }
DINLINE float tanh_fast(float v) {
    float e = __expf(2.0f * fabsf(v));
    return copysignf(1.0f - __fdividef(2.0f, e + 1.0f), v);
}
DINLINE void cl_sync() {
    asm volatile("barrier.cluster.arrive.aligned;" ::: "memory");
    asm volatile("barrier.cluster.wait.aligned;" ::: "memory");
}
DINLINE uint32_t mapa_u32(uint32_t a, uint32_t r) {
    uint32_t p; asm("mapa.shared::cluster.u32 %0, %1, %2;" : "=r"(p) : "r"(a), "r"(r));
    return p;
}
DINLINE void st_rem64(uint32_t a, ull v) {
    asm volatile("st.shared::cluster.b64 [%0], %1;" :: "r"(a), "l"(v) : "memory");
}
DINLINE ull pk2(float a, float b) {
    ull r; asm("mov.b64 %0, {%1, %2};" : "=l"(r) : "f"(a), "f"(b)); return r;
}
DINLINE float2 upk(ull v) {
    float2 r; asm("mov.b64 {%0, %1}, %2;" : "=f"(r.x), "=f"(r.y) : "l"(v)); return r;
}
DINLINE void f2(ull& d, ull a, ull b) {
    asm("fma.rn.f32x2 %0, %1, %2, %0;" : "+l"(d) : "l"(a), "l"(b));
}
DINLINE void mb_init(uint32_t a, uint32_t n) {
    asm volatile("mbarrier.init.shared.b64 [%0], %1;" :: "r"(a), "r"(n) : "memory");
}
DINLINE void mb_arrive_rel(uint32_t laddr, uint32_t rank) {
    asm volatile("{ .reg .b32 ra;\n\t"
        "mapa.shared::cluster.u32 ra, %0, %1;\n\t"
        "mbarrier.arrive.release.cluster.shared::cluster.b64 _, [ra]; }"
        :: "r"(laddr), "r"(rank) : "memory");
}
DINLINE void mb_wait(uint32_t a, uint32_t par) {
    asm volatile("{ .reg .pred P;\n"
        "W%=:\n\t"
        "mbarrier.try_wait.parity.acquire.cluster.shared::cta.b64 P, [%0], %1, 0x989680;\n\t"
        "@P bra.uni D%=;\n\t"
        "bra.uni W%=;\n"
        "D%=: }" :: "r"(a), "r"(par) : "memory");
}

__global__ void __launch_bounds__(NTHR, 1) __cluster_dims__(CL, 1, 1)
gru_stack_kernel(const float* __restrict__ x,  const float* __restrict__ k1,
                 const float* __restrict__ r1, const float* __restrict__ b1,
                 const float* __restrict__ k2, const float* __restrict__ r2,
                 const float* __restrict__ b2, const float* __restrict__ w3,
                 const float* __restrict__ b3, const float* __restrict__ w4,
                 const float* __restrict__ b4, const float* __restrict__ w5,
                 const float* __restrict__ b5, float* __restrict__ out)
{
    extern __shared__ float sm[];
    const int tid = threadIdx.x;
    const int c = blockIdx.x & (CL - 1);
    const int g = blockIdx.x >> 3;
    const int row = tid >> 3, ct = tid & 7;

    uint32_t smem_base;
    asm("{ .reg .u64 t; cvta.to.shared.u64 t, %1; cvt.u32.u64 %0, t; }"
        : "=r"(smem_base) : "l"(sm));
    const uint32_t mbFREE = smem_base, mbRDY1 = smem_base + 8, mbRDY2 = smem_base + 16;
    if (tid == 0) { mb_init(mbFREE, 8); mb_init(mbRDY1, 8); mb_init(mbRDY2, 8); }

    // ---- Stage weights, gate-interleaved: row k = 8 groups x [4z|4r|4h] ----
    for (int idx = tid; idx < 24576; idx += NTHR) {
        int k = idx / 96, j = idx % 96, gg = j / 12, q = j % 12;
        sm[OFF_R1 + idx] = r1[k * 768 + (q >> 2) * 256 + (c << 5) + (gg << 2) + (q & 3)];
    }
    for (int idx = tid; idx < 6144; idx += NTHR) {
        int k = idx / 96, j = idx % 96, gg = j / 12, q = j % 12;
        sm[OFF_K1 + idx] = k1[k * 768 + (q >> 2) * 256 + (c << 5) + (gg << 2) + (q & 3)];
    }
    for (int idx = tid; idx < 12288; idx += NTHR) {   // K2: 8 groups x [2z|2r|2h]
        int k = idx / 48, j = idx % 48, gg = j / 6, q = j % 6;
        sm[OFF_K2 + idx] = k2[k * 384 + (q >> 1) * 128 + (c << 4) + (gg << 1) + (q & 1)];
    }
    for (int idx = tid; idx < 6144; idx += NTHR) {
        int k = idx / 48, j = idx % 48, gg = j / 6, q = j % 6;
        sm[OFF_R2 + idx] = r2[k * 384 + (q >> 1) * 128 + (c << 4) + (gg << 1) + (q & 1)];
    }
    for (int idx = tid; idx < Br * H1S; idx += NTHR) sm[OFF_H1 + idx] = 0.0f;
    for (int idx = tid; idx < Br * H2S; idx += NTHR) sm[OFF_H2 + idx] = 0.0f;
    #pragma unroll
    for (int j = 0; j < 2; j++) {   // x(0)
        int i = tid * 2 + j, r = i >> 4, f4 = i & 15;
        *(float4*)(sm + OFF_XS + r * XSS + f4 * 4) =
            *(const float4*)(x + ((size_t)(g * Br + r) * Tlen) * 64 + f4 * 4);
    }

    // ---- biases (registers) ----
    ull Bz0, Bz1, Br0, Br1, Bx0, Bx1, Bh0, Bh1;
    {
        int u = (c << 5) + ct * 4;
        Bz0 = pk2(b1[u] + b1[768 + u],     b1[u+1] + b1[769 + u]);
        Bz1 = pk2(b1[u+2] + b1[770 + u],   b1[u+3] + b1[771 + u]);
        Br0 = pk2(b1[256+u] + b1[1024+u],  b1[257+u] + b1[1025+u]);
        Br1 = pk2(b1[258+u] + b1[1026+u],  b1[259+u] + b1[1027+u]);
        Bx0 = pk2(b1[512+u], b1[513+u]);   Bx1 = pk2(b1[514+u], b1[515+u]);
        Bh0 = pk2(b1[1280+u], b1[1281+u]); Bh1 = pk2(b1[1282+u], b1[1283+u]);
    }
    ull Cz, Cr, Cx, Ch;
    {
        int u = (c << 4) + ct * 2;
        Cz = pk2(b2[u] + b2[384+u],       b2[u+1] + b2[385+u]);
        Cr = pk2(b2[128+u] + b2[512+u],   b2[129+u] + b2[513+u]);
        Cx = pk2(b2[256+u], b2[257+u]);
        Ch = pk2(b2[640+u], b2[641+u]);
    }

    // ---- precomputed remote addresses ----
    const uint32_t h1la = smem_base + (uint32_t)(OFF_H1 + row * H1S + (c << 5) + ct * 4) * 4u;
    const uint32_t h2la = smem_base + (uint32_t)(OFF_H2 + row * H2S + (c << 4) + ct * 2) * 4u;
    uint32_t map1[CL], map2[CL];
    #pragma unroll
    for (int rk = 0; rk < CL; rk++) { map1[rk] = mapa_u32(h1la, rk); map2[rk] = mapa_u32(h2la, rk); }

    const ull* Wr1 = (const ull*)(sm + OFF_R1);
    const ull* Wk1 = (const ull*)(sm + OFF_K1);
    const ull* Wk2 = (const ull*)(sm + OFF_K2);
    const ull* Wr2 = (const ull*)(sm + OFF_R2);
    const float* h1row = sm + OFF_H1 + row * H1S;
    const float* h2row = sm + OFF_H2 + row * H2S;
    const float* xrow  = sm + OFF_XS + row * XSS;

    float hp[4] = {0, 0, 0, 0};
    float hq[2] = {0, 0};

    __syncthreads();
    cl_sync();   // inits + weights visible cluster-wide

    for (int t = 0; t < Tlen; t++) {
        const uint32_t par = (uint32_t)(t & 1);
        float4 xr0, xr1;
        if (t + 1 < Tlen) {
            int i0 = tid * 2, r0 = i0 >> 4, f0 = i0 & 15;
            xr0 = *(const float4*)(x + ((size_t)(g * Br + r0) * Tlen + t + 1) * 64 + f0 * 4);
            int i1 = i0 + 1, r1i = i1 >> 4, f1 = i1 & 15;
            xr1 = *(const float4*)(x + ((size_t)(g * Br + r1i) * Tlen + t + 1) * 64 + f1 * 4);
        }

        // ---- GRU1: full projections for 4 owned units ----
        ull az0 = Bz0, az1 = Bz1, ar0 = Br0, ar1 = Br1;
        ull ax0 = Bx0, ax1 = Bx1, ah0 = Bh0, ah1 = Bh1;
        #pragma unroll 4
        for (int k = 0; k < 64; k++) {       // x @ k1
            ull v = pk2(xrow[k], xrow[k]);
            const ull* p = Wk1 + k * 48 + ct * 6;
            ulonglong2 wz = *(const ulonglong2*)(p);
            ulonglong2 wr = *(const ulonglong2*)(p + 2);
            ulonglong2 wh = *(const ulonglong2*)(p + 4);
            f2(az0, v, wz.x); f2(az1, v, wz.y);
            f2(ar0, v, wr.x); f2(ar1, v, wr.y);
            f2(ax0, v, wh.x); f2(ax1, v, wh.y);
        }
        #pragma unroll 4
        for (int k = 0; k < 256; k++) {      // h1(t-1) @ r1
            ull v = pk2(h1row[k], h1row[k]);
            const ull* p = Wr1 + k * 48 + ct * 6;
            ulonglong2 wz = *(const ulonglong2*)(p);
            ulonglong2 wr = *(const ulonglong2*)(p + 2);
            ulonglong2 wh = *(const ulonglong2*)(p + 4);
            f2(az0, v, wz.x); f2(az1, v, wz.y);
            f2(ar0, v, wr.x); f2(ar1, v, wr.y);
            f2(ah0, v, wh.x); f2(ah1, v, wh.y);
        }

        // ---- GRU2 recurrent projection (h2(t-1) @ r2) ----
        if (t > 0) mb_wait(mbRDY2, (uint32_t)((t - 1) & 1));
        ull cz = Cz, cr = Cr, cx = Cx, ch = Ch;
        #pragma unroll 4
        for (int k = 0; k < 128; k++) {
            ull v = pk2(h2row[k], h2row[k]);
            const ull* p = Wr2 + k * 24 + ct * 3;
            f2(cz, v, p[0]); f2(cr, v, p[1]); f2(ch, v, p[2]);
        }
        __syncthreads();                     // S1: all reads of h1(t-1), h2(t-1), x(t) done
        if (tid < 8) mb_arrive_rel(mbFREE, (uint32_t)tid);
        if (t + 1 < Tlen) {
            int i0 = tid * 2, r0 = i0 >> 4, f0 = i0 & 15;
            *(float4*)(sm + OFF_XS + r0 * XSS + f0 * 4) = xr0;
            int i1 = i0 + 1, r1i = i1 >> 4, f1 = i1 & 15;
            *(float4*)(sm + OFF_XS + r1i * XSS + f1 * 4) = xr1;
        }

        // ---- GRU1 gates (all local) ----
        {
            float2 vz0 = upk(az0), vz1 = upk(az1), vr0 = upk(ar0), vr1 = upk(ar1);
            float2 vx0 = upk(ax0), vx1 = upk(ax1), vh0 = upk(ah0), vh1 = upk(ah1);
            float zz[4] = {sigf(vz0.x), sigf(vz0.y), sigf(vz1.x), sigf(vz1.y)};
            float rr[4] = {sigf(vr0.x), sigf(vr0.y), sigf(vr1.x), sigf(vr1.y)};
            float xx[4] = {vx0.x, vx0.y, vx1.x, vx1.y};
            float hh[4] = {vh0.x, vh0.y, vh1.x, vh1.y};
            #pragma unroll
            for (int i = 0; i < 4; i++) {
                float cand = tanh_fast(xx[i] + rr[i] * hh[i]);
                hp[i] = zz[i] * hp[i] + (1.0f - zz[i]) * cand;
            }
        }
        mb_wait(mbFREE, par);                // WAR cluster-wide
        {
            ull q0 = pk2(hp[0], hp[1]), q1 = pk2(hp[2], hp[3]);
            #pragma unroll
            for (int rk = 0; rk < CL; rk++) { st_rem64(map1[rk], q0); st_rem64(map1[rk] + 8, q1); }
        }
        __syncthreads();                     // S2: all h1 stores issued
        if (tid < 8) mb_arrive_rel(mbRDY1, (uint32_t)tid);
        mb_wait(mbRDY1, par);                // h1(t) visible locally

        // ---- GRU2 input projection (h1(t) @ k2) ----
        #pragma unroll 4
        for (int k = 0; k < 256; k++) {
            ull v = pk2(h1row[k], h1row[k]);
            const ull* p = Wk2 + k * 24 + ct * 3;
            f2(cz, v, p[0]); f2(cr, v, p[1]); f2(cx, v, p[2]);
        }
        // ---- GRU2 gates + publish ----
        {
            float2 vz = upk(cz), vr = upk(cr), vx = upk(cx), vh = upk(ch);
            float z0 = sigf(vz.x), r0 = sigf(vr.x);
            float z1 = sigf(vz.y), r1g = sigf(vr.y);
            hq[0] = z0 * hq[0] + (1.0f - z0) * tanh_fast(vx.x + r0 * vh.x);
            hq[1] = z1 * hq[1] + (1.0f - z1) * tanh_fast(vx.y + r1g * vh.y);
            ull q = pk2(hq[0], hq[1]);
            #pragma unroll
            for (int rk = 0; rk < CL; rk++) st_rem64(map2[rk], q);
        }
        __syncthreads();                     // S3: all h2 stores issued
        if (tid < 8) mb_arrive_rel(mbRDY2, (uint32_t)tid);
    }
    mb_wait(mbRDY2, (uint32_t)((Tlen - 1) & 1));   // final h2 delivered everywhere

    // ---- Dense head (rank 0 CTAs) ----
    if (c == 0) {
        float* sD3 = sm + OFF_XS;            // [16][64] (x buffer dead)
        float* sD4 = sm + OFF_H1;            // [16][32] (h1 dead)
        __syncthreads();
        for (int idx = tid; idx < Br * 64; idx += NTHR) {
            int r = idx >> 6, o = idx & 63;
            float a = b3[o];
            #pragma unroll 8
            for (int k = 0; k < 128; k++) a += sm[OFF_H2 + r * H2S + k] * w3[k * 64 + o];
            sD3[idx] = a;
        }
        __syncthreads();
        for (int idx = tid; idx < Br * 32; idx += NTHR) {
            int r = idx >> 5, o = idx & 31;
            float a = b4[o];
            #pragma unroll 8
            for (int k = 0; k < 64; k++) a += sD3[r * 64 + k] * w4[k * 32 + o];
            sD4[idx] = a;
        }
        __syncthreads();
        for (int idx = tid; idx < Br * OUTW; idx += NTHR) {
            int r = idx / OUTW, o = idx % OUTW;
            float a = b5[o];
            #pragma unroll 8
            for (int k = 0; k < 32; k++) a += sD4[r * 32 + k] * w5[k * OUTW + o];
            out[(g * Br + r) * OUTW + o] = a;
        }
    }
}

extern "C" void kernel_launch(void* const* d_in, const int* in_sizes, int n_in,
                              void* d_out, int out_size) {
    (void)in_sizes; (void)n_in; (void)out_size;
    const float* x  = (const float*)d_in[0];
    const float* k1 = (const float*)d_in[1];
    const float* r1 = (const float*)d_in[2];
    const float* b1 = (const float*)d_in[3];
    const float* k2 = (const float*)d_in[4];
    const float* r2 = (const float*)d_in[5];
    const float* b2 = (const float*)d_in[6];
    const float* w3 = (const float*)d_in[7];
    const float* b3 = (const float*)d_in[8];
    const float* w4 = (const float*)d_in[9];
    const float* b4 = (const float*)d_in[10];
    const float* w5 = (const float*)d_in[11];
    const float* b5 = (const float*)d_in[12];
    float* out = (float*)d_out;

    cudaFuncSetAttribute(gru_stack_kernel,
                         cudaFuncAttributeMaxDynamicSharedMemorySize, (int)SMEM_BYTES);
    gru_stack_kernel<<<128, NTHR, SMEM_BYTES>>>(
        x, k1, r1, b1, k2, r2, b2, w3, b3, w4, b4, w5, b5, out);
}